// round 12
// baseline (speedup 1.0000x reference)
#include <cuda_runtime.h>
#include <cuda_fp16.h>
#include <cstdint>

#define BATCH 8
#define LQ 2048
#define LY 2048
#define DIM 64
#define EPSN 1e-8f

#define RS 72                     // tile row stride in halves (144 B)
#define TILE_HB (128 * RS * 2)    // 18432 B per operand tile
#define STAGE_B (2 * TILE_HB)     // A + B per pipeline stage = 36864 B
#define SM_TOTAL (2 * STAGE_B)    // double-buffered = 73728 B dynamic smem

#define NCTA 296                  // 148 SMs x 2 CTAs: one full wave
#define NTILES 2048               // 8 b x 16 qt x 16 yt (128x128 tiles)

// fp16 normalized operands (validated error ~2.9e-4 rel vs 1e-3 gate)
__device__ __half g_q[(size_t)BATCH * LQ * DIM];
__device__ __half g_y[(size_t)BATCH * LY * DIM];

__device__ __forceinline__ uint32_t smem_u32(const void* p) {
    uint32_t a;
    asm("{ .reg .u64 t; cvta.to.shared.u64 t, %1; cvt.u32.u64 %0, t; }"
        : "=r"(a) : "l"(p));
    return a;
}
__device__ __forceinline__ void atomicMaxFloat(float* addr, float v) {
    if (v >= 0.0f)
        atomicMax((int*)addr, __float_as_int(v));
    else
        atomicMin((unsigned int*)addr, __float_as_uint(v));
}

#define LDSM_X4(r0, r1, r2, r3, addr)                                          \
    asm volatile("ldmatrix.sync.aligned.m8n8.x4.shared.b16 {%0,%1,%2,%3}, [%4];" \
                 : "=r"(r0), "=r"(r1), "=r"(r2), "=r"(r3) : "r"(addr))

#define MMA_F16(d, a, bf)                                                      \
    asm volatile(                                                              \
        "mma.sync.aligned.m16n8k16.row.col.f32.f16.f16.f32 "                  \
        "{%0,%1,%2,%3}, {%4,%5,%6,%7}, {%8,%9}, {%0,%1,%2,%3};"               \
        : "+f"(d[0]), "+f"(d[1]), "+f"(d[2]), "+f"(d[3])                       \
        : "r"(a[0]), "r"(a[1]), "r"(a[2]), "r"(a[3]), "r"(bf[0]), "r"(bf[1]))

#define CP_ASYNC_CG16(smaddr, gptr)                                            \
    asm volatile("cp.async.cg.shared.global [%0], [%1], 16;"                    \
                 :: "r"(smaddr), "l"(gptr))

// ---------------------------------------------------------------------------
// Prep: normalize -> fp16. 4 rows per warp. Also inits sim on q rows.
// ---------------------------------------------------------------------------
__global__ void prep_kernel(const float* __restrict__ q,
                            const float* __restrict__ y,
                            float* __restrict__ sim) {
    int gw   = (blockIdx.x * blockDim.x + threadIdx.x) >> 5;
    int lane = threadIdx.x & 31;
    int r    = gw * 4 + (lane >> 3);
    int j    = lane & 7;
    const int rows = BATCH * LQ;
    if (r >= 2 * rows) return;
    bool isQ = r < rows;
    int row  = isQ ? r : r - rows;

    const float4* src = (const float4*)((isQ ? q : y) + (size_t)row * DIM);
    float4 v1 = src[j * 2];
    float4 v2 = src[j * 2 + 1];
    float ss = v1.x * v1.x + v1.y * v1.y + v1.z * v1.z + v1.w * v1.w +
               v2.x * v2.x + v2.y * v2.y + v2.z * v2.z + v2.w * v2.w;
    ss += __shfl_xor_sync(0xffffffffu, ss, 1);
    ss += __shfl_xor_sync(0xffffffffu, ss, 2);
    ss += __shfl_xor_sync(0xffffffffu, ss, 4);
    float inv = 1.0f / fmaxf(sqrtf(ss), EPSN);

    __half2 h[4];
    h[0] = __floats2half2_rn(v1.x * inv, v1.y * inv);
    h[1] = __floats2half2_rn(v1.z * inv, v1.w * inv);
    h[2] = __floats2half2_rn(v2.x * inv, v2.y * inv);
    h[3] = __floats2half2_rn(v2.z * inv, v2.w * inv);
    __half* dst = (isQ ? g_q : g_y) + (size_t)row * DIM + j * 8;
    *(uint4*)dst = *(uint4*)h;
    if (isQ && j == 0) sim[row] = __int_as_float(0xff800000);
}

// ---------------------------------------------------------------------------
// Persistent HMMA GEMM: 296 CTAs stride over 2048 128x128 tiles with a
// double-buffered cp.async pipeline (prefetch tile j+2 during epilogue of j).
// 8 warps (4x2), warp tile 32x64. Direct STG.64 epilogue + fused row-max.
// ---------------------------------------------------------------------------
__global__ __launch_bounds__(256, 2)
void gemm_kernel(float* __restrict__ att, float* __restrict__ sim) {
    extern __shared__ char smem[];
    const uint32_t s0 = smem_u32(smem);

    const int tid  = threadIdx.x;
    const int lane = tid & 31;
    const int wid  = tid >> 5;
    const int wm   = wid & 3;    // q group (32 rows)
    const int wn   = wid >> 2;   // y group (64 cols)
    const int c    = blockIdx.x;

    // Fill one pipeline stage (A + B for tile i) via cp.async.cg.
    auto fill = [&](int i, int p) {
        int b = i >> 8, r = i & 255;
        const float4* qs =
            (const float4*)(g_q + ((size_t)b * LQ + ((r >> 4) << 7)) * DIM);
        const float4* ys =
            (const float4*)(g_y + ((size_t)b * LY + ((r & 15) << 7)) * DIM);
        uint32_t sA = s0 + p * STAGE_B;
        uint32_t sB = sA + TILE_HB;
#pragma unroll
        for (int it = 0; it < 4; it++) {
            int idx = it * 256 + tid;        // 0..1023 float4s
            int row = idx >> 3, cc = idx & 7;
            uint32_t off = row * (RS * 2) + cc * 16;
            CP_ASYNC_CG16(sA + off, qs + idx);
            CP_ASYNC_CG16(sB + off, ys + idx);
        }
    };

    // Prologue: stage tiles c and c+296.
    fill(c, 0);
    asm volatile("cp.async.commit_group;" ::: "memory");
    fill(c + NCTA, 1);
    asm volatile("cp.async.commit_group;" ::: "memory");

    // ldmatrix offsets relative to stage base.
    uint32_t aoff[2];
#pragma unroll
    for (int mi = 0; mi < 2; mi++)
        aoff[mi] = (wm * 32 + mi * 16 + (lane & 15)) * (RS * 2) +
                   ((lane >> 4) & 1) * 16;
    uint32_t boff[4];
#pragma unroll
    for (int np = 0; np < 4; np++)
        boff[np] = TILE_HB +
                   (wn * 64 + np * 16 + (lane & 7) + ((lane >> 4) & 1) * 8) *
                       (RS * 2) +
                   ((lane >> 3) & 1) * 16;

    const int qlane = lane >> 2;
    const int npair = lane & 3;
    const int nmy   = (NTILES - c + NCTA - 1) / NCTA;   // 6 or 7 tiles

    for (int j = 0; j < nmy; j++) {
        // tile j (group j) ready once <=1 group outstanding (uniform commits)
        asm volatile("cp.async.wait_group 1;" ::: "memory");
        __syncthreads();

        const uint32_t base = s0 + (j & 1) * STAGE_B;
        float acc[2][8][4];
#pragma unroll
        for (int mi = 0; mi < 2; mi++)
#pragma unroll
            for (int ni = 0; ni < 8; ni++)
#pragma unroll
                for (int e = 0; e < 4; e++) acc[mi][ni][e] = 0.0f;

#pragma unroll
        for (int ks = 0; ks < 4; ks++) {
            uint32_t bf[8][2];
#pragma unroll
            for (int np = 0; np < 4; np++)
                LDSM_X4(bf[2 * np][0], bf[2 * np][1], bf[2 * np + 1][0],
                        bf[2 * np + 1][1], base + boff[np] + ks * 32);
            uint32_t a[2][4];
#pragma unroll
            for (int mi = 0; mi < 2; mi++)
                LDSM_X4(a[mi][0], a[mi][1], a[mi][2], a[mi][3],
                        base + aoff[mi] + ks * 32);
#pragma unroll
            for (int mi = 0; mi < 2; mi++)
#pragma unroll
                for (int ni = 0; ni < 8; ni++)
                    MMA_F16(acc[mi][ni], a[mi], bf[ni]);
        }

        // All warps done reading this stage -> safe to refill it.
        __syncthreads();
        int nexti = c + (j + 2) * NCTA;
        if (nexti < NTILES) fill(nexti, j & 1);
        asm volatile("cp.async.commit_group;" ::: "memory");  // always commit

        // Epilogue (overlaps the async prefetch): stores + fused row-max.
        int i = c + j * NCTA;
        int b = i >> 8, r = i & 255;
        int qt = (r >> 4) << 7, yt = (r & 15) << 7;
#pragma unroll
        for (int mi = 0; mi < 2; mi++) {
#pragma unroll
            for (int h = 0; h < 2; h++) {
                int qrow = qt + wm * 32 + mi * 16 + h * 8 + qlane;
                float* outr = att + ((size_t)b * LQ + qrow) * LY + yt +
                              wn * 64 + npair * 2;
                float m = __int_as_float(0xff800000);
#pragma unroll
                for (int ni = 0; ni < 8; ni++) {
                    float c0 = acc[mi][ni][2 * h];
                    float c1 = acc[mi][ni][2 * h + 1];
                    __stcs((float2*)(outr + ni * 8), make_float2(c0, c1));
                    m = fmaxf(m, fmaxf(c0, c1));
                }
                m = fmaxf(m, __shfl_xor_sync(0xffffffffu, m, 1));
                m = fmaxf(m, __shfl_xor_sync(0xffffffffu, m, 2));
                if (npair == 0)
                    atomicMaxFloat(&sim[(size_t)b * LQ + qrow], m);
            }
        }
    }
}

// ---------------------------------------------------------------------------
extern "C" void kernel_launch(void* const* d_in, const int* in_sizes, int n_in,
                              void* d_out, int out_size) {
    const float* q = (const float*)d_in[0];
    const float* y = (const float*)d_in[1];
    float* att = (float*)d_out;
    float* sim = att + (size_t)BATCH * LQ * LY;

    static bool attr_done = false;
    if (!attr_done) {
        cudaFuncSetAttribute(gemm_kernel,
                             cudaFuncAttributeMaxDynamicSharedMemorySize,
                             SM_TOTAL);
        attr_done = true;
    }

    int warps = (2 * BATCH * LQ) / 4;
    prep_kernel<<<(warps * 32 + 255) / 256, 256>>>(q, y, sim);

    gemm_kernel<<<NCTA, 256, SM_TOTAL>>>(att, sim);
}

// round 13
// speedup vs baseline: 1.0649x; 1.0649x over previous
#include <cuda_runtime.h>
#include <cuda_fp16.h>
#include <cstdint>

#define BATCH 8
#define LQ 2048
#define LY 2048
#define DIM 64
#define EPSN 1e-8f

#define RS 72                     // tile row stride in halves (144 B)
#define TILE_A_HB (64 * RS * 2)   // 9216 B  (A: 64 q rows)
#define TILE_B_HB (128 * RS * 2)  // 18432 B (B: 128 y rows)
#define SM_TOTAL (TILE_A_HB + TILE_B_HB)   // 27648 B dynamic smem

// fp16 normalized operands (validated error ~2.9e-4 rel vs 1e-3 gate)
__device__ __half g_q[(size_t)BATCH * LQ * DIM];
__device__ __half g_y[(size_t)BATCH * LY * DIM];

__device__ __forceinline__ uint32_t smem_u32(const void* p) {
    uint32_t a;
    asm("{ .reg .u64 t; cvta.to.shared.u64 t, %1; cvt.u32.u64 %0, t; }"
        : "=r"(a) : "l"(p));
    return a;
}
__device__ __forceinline__ void atomicMaxFloat(float* addr, float v) {
    if (v >= 0.0f)
        atomicMax((int*)addr, __float_as_int(v));
    else
        atomicMin((unsigned int*)addr, __float_as_uint(v));
}

#define LDSM_X4(r0, r1, r2, r3, addr)                                          \
    asm volatile("ldmatrix.sync.aligned.m8n8.x4.shared.b16 {%0,%1,%2,%3}, [%4];" \
                 : "=r"(r0), "=r"(r1), "=r"(r2), "=r"(r3) : "r"(addr))

#define MMA_F16(d, a, bf)                                                      \
    asm volatile(                                                              \
        "mma.sync.aligned.m16n8k16.row.col.f32.f16.f16.f32 "                  \
        "{%0,%1,%2,%3}, {%4,%5,%6,%7}, {%8,%9}, {%0,%1,%2,%3};"               \
        : "+f"(d[0]), "+f"(d[1]), "+f"(d[2]), "+f"(d[3])                       \
        : "r"(a[0]), "r"(a[1]), "r"(a[2]), "r"(a[3]), "r"(bf[0]), "r"(bf[1]))

#define CP_ASYNC_CG16(smaddr, gptr)                                            \
    asm volatile("cp.async.cg.shared.global [%0], [%1], 16;"                    \
                 :: "r"(smaddr), "l"(gptr))

// ---------------------------------------------------------------------------
// Prep: normalize -> fp16. 4 rows per warp. Also inits sim on q rows.
// ---------------------------------------------------------------------------
__global__ void prep_kernel(const float* __restrict__ q,
                            const float* __restrict__ y,
                            float* __restrict__ sim) {
    int gw   = (blockIdx.x * blockDim.x + threadIdx.x) >> 5;
    int lane = threadIdx.x & 31;
    int r    = gw * 4 + (lane >> 3);
    int j    = lane & 7;
    const int rows = BATCH * LQ;
    if (r >= 2 * rows) return;
    bool isQ = r < rows;
    int row  = isQ ? r : r - rows;

    const float4* src = (const float4*)((isQ ? q : y) + (size_t)row * DIM);
    float4 v1 = src[j * 2];
    float4 v2 = src[j * 2 + 1];
    float ss = v1.x * v1.x + v1.y * v1.y + v1.z * v1.z + v1.w * v1.w +
               v2.x * v2.x + v2.y * v2.y + v2.z * v2.z + v2.w * v2.w;
    ss += __shfl_xor_sync(0xffffffffu, ss, 1);
    ss += __shfl_xor_sync(0xffffffffu, ss, 2);
    ss += __shfl_xor_sync(0xffffffffu, ss, 4);
    float inv = 1.0f / fmaxf(sqrtf(ss), EPSN);

    __half2 h[4];
    h[0] = __floats2half2_rn(v1.x * inv, v1.y * inv);
    h[1] = __floats2half2_rn(v1.z * inv, v1.w * inv);
    h[2] = __floats2half2_rn(v2.x * inv, v2.y * inv);
    h[3] = __floats2half2_rn(v2.z * inv, v2.w * inv);
    __half* dst = (isQ ? g_q : g_y) + (size_t)row * DIM + j * 8;
    *(uint4*)dst = *(uint4*)h;
    if (isQ && j == 0) sim[row] = __int_as_float(0xff800000);
}

// ---------------------------------------------------------------------------
// HMMA GEMM: CTA = 64(q) x 128(y), 4 warps (2x2), warp tile 32x64 (unchanged
// economics vs best kernel). 4 CTAs/SM for fine-grained phase overlap.
// ---------------------------------------------------------------------------
__global__ __launch_bounds__(128, 4)
void gemm_kernel(float* __restrict__ att, float* __restrict__ sim) {
    extern __shared__ char smem[];
    const uint32_t smA = smem_u32(smem);
    const uint32_t smB = smA + TILE_A_HB;

    const int tid  = threadIdx.x;
    const int lane = tid & 31;
    const int wid  = tid >> 5;
    const int wm   = wid & 1;    // q group (32 rows)
    const int wn   = wid >> 1;   // y group (64 cols)

    const int b  = blockIdx.z;
    const int yt = blockIdx.x * 128;
    const int qt = blockIdx.y * 64;

    // --- async fills: A 512 float4, B 1024 float4, 128 threads ---
    const float4* qsrc = (const float4*)(g_q + ((size_t)b * LQ + qt) * DIM);
    const float4* ysrc = (const float4*)(g_y + ((size_t)b * LY + yt) * DIM);
#pragma unroll
    for (int it = 0; it < 4; it++) {
        int idx = it * 128 + tid;           // 0..511
        int row = idx >> 3, c = idx & 7;
        CP_ASYNC_CG16(smA + row * (RS * 2) + c * 16, qsrc + idx);
    }
#pragma unroll
    for (int it = 0; it < 8; it++) {
        int idx = it * 128 + tid;           // 0..1023
        int row = idx >> 3, c = idx & 7;
        CP_ASYNC_CG16(smB + row * (RS * 2) + c * 16, ysrc + idx);
    }
    asm volatile("cp.async.commit_group;" ::: "memory");

    uint32_t aaddr[2];
#pragma unroll
    for (int mi = 0; mi < 2; mi++) {
        int row = wm * 32 + mi * 16 + (lane & 15);
        aaddr[mi] = smA + row * (RS * 2) + ((lane >> 4) & 1) * 16;
    }
    uint32_t baddr[4];
#pragma unroll
    for (int np = 0; np < 4; np++) {
        int n = wn * 64 + np * 16 + (lane & 7) + ((lane >> 4) & 1) * 8;
        baddr[np] = smB + n * (RS * 2) + ((lane >> 3) & 1) * 16;
    }

    float acc[2][8][4];
#pragma unroll
    for (int mi = 0; mi < 2; mi++)
#pragma unroll
        for (int ni = 0; ni < 8; ni++)
#pragma unroll
            for (int e = 0; e < 4; e++) acc[mi][ni][e] = 0.0f;

    asm volatile("cp.async.wait_group 0;" ::: "memory");
    __syncthreads();

#pragma unroll
    for (int ks = 0; ks < 4; ks++) {
        uint32_t bf[8][2];
#pragma unroll
        for (int np = 0; np < 4; np++)
            LDSM_X4(bf[2 * np][0], bf[2 * np][1], bf[2 * np + 1][0],
                    bf[2 * np + 1][1], baddr[np] + ks * 32);
        uint32_t a[2][4];
#pragma unroll
        for (int mi = 0; mi < 2; mi++)
            LDSM_X4(a[mi][0], a[mi][1], a[mi][2], a[mi][3],
                    aaddr[mi] + ks * 32);
#pragma unroll
        for (int mi = 0; mi < 2; mi++)
#pragma unroll
            for (int ni = 0; ni < 8; ni++)
                MMA_F16(acc[mi][ni], a[mi], bf[ni]);
    }

    // --- Epilogue: direct streaming stores + fused row-max ---
    const int qlane = lane >> 2;
    const int npair = lane & 3;
#pragma unroll
    for (int mi = 0; mi < 2; mi++) {
#pragma unroll
        for (int h = 0; h < 2; h++) {
            int qrow = qt + wm * 32 + mi * 16 + h * 8 + qlane;
            float* outr = att + ((size_t)b * LQ + qrow) * LY + yt + wn * 64 +
                          npair * 2;
            float m = __int_as_float(0xff800000);
#pragma unroll
            for (int ni = 0; ni < 8; ni++) {
                float c0 = acc[mi][ni][2 * h];
                float c1 = acc[mi][ni][2 * h + 1];
                __stcs((float2*)(outr + ni * 8), make_float2(c0, c1));
                m = fmaxf(m, fmaxf(c0, c1));
            }
            m = fmaxf(m, __shfl_xor_sync(0xffffffffu, m, 1));
            m = fmaxf(m, __shfl_xor_sync(0xffffffffu, m, 2));
            if (npair == 0)
                atomicMaxFloat(&sim[(size_t)b * LQ + qrow], m);
        }
    }
}

// ---------------------------------------------------------------------------
extern "C" void kernel_launch(void* const* d_in, const int* in_sizes, int n_in,
                              void* d_out, int out_size) {
    const float* q = (const float*)d_in[0];
    const float* y = (const float*)d_in[1];
    float* att = (float*)d_out;
    float* sim = att + (size_t)BATCH * LQ * LY;

    int warps = (2 * BATCH * LQ) / 4;
    prep_kernel<<<(warps * 32 + 255) / 256, 256>>>(q, y, sim);

    dim3 grid(LY / 128, LQ / 64, BATCH);   // (16, 32, 8) = 4096 CTAs
    gemm_kernel<<<grid, 128, SM_TOTAL>>>(att, sim);
}

// round 14
// speedup vs baseline: 1.1080x; 1.0405x over previous
#include <cuda_runtime.h>
#include <cuda_fp16.h>
#include <cstdint>

#define BATCH 8
#define LQ 2048
#define LY 2048
#define DIM 64
#define EPSN 1e-8f

#define RS 72                    // tile row stride in halves (144 B)
#define TILE_HB (128 * RS * 2)   // 18432 B per tile
#define SM_TOTAL (3 * TILE_HB)   // A + 2 B tiles = 55296 B dynamic smem

// fp16 normalized operands (input quantization err ~2.9e-4; +fp16 acc ~5.4e-4)
__device__ __half g_q[(size_t)BATCH * LQ * DIM];
__device__ __half g_y[(size_t)BATCH * LY * DIM];

__device__ __forceinline__ uint32_t smem_u32(const void* p) {
    uint32_t a;
    asm("{ .reg .u64 t; cvta.to.shared.u64 t, %1; cvt.u32.u64 %0, t; }"
        : "=r"(a) : "l"(p));
    return a;
}
__device__ __forceinline__ void atomicMaxFloat(float* addr, float v) {
    if (v >= 0.0f)
        atomicMax((int*)addr, __float_as_int(v));
    else
        atomicMin((unsigned int*)addr, __float_as_uint(v));
}

#define LDSM_X4(r0, r1, r2, r3, addr)                                          \
    asm volatile("ldmatrix.sync.aligned.m8n8.x4.shared.b16 {%0,%1,%2,%3}, [%4];" \
                 : "=r"(r0), "=r"(r1), "=r"(r2), "=r"(r3) : "r"(addr))

// fp16-accumulator MMA: D/C are 2 packed half2 regs (rows l>>2 and l>>2+8).
#define MMA_F16ACC(d, a, bf)                                                   \
    asm volatile(                                                              \
        "mma.sync.aligned.m16n8k16.row.col.f16.f16.f16.f16 "                  \
        "{%0,%1}, {%2,%3,%4,%5}, {%6,%7}, {%0,%1};"                           \
        : "+r"(d[0]), "+r"(d[1])                                               \
        : "r"(a[0]), "r"(a[1]), "r"(a[2]), "r"(a[3]), "r"(bf[0]), "r"(bf[1]))

#define CP_ASYNC_CG16(smaddr, gptr)                                            \
    asm volatile("cp.async.cg.shared.global [%0], [%1], 16;"                    \
                 :: "r"(smaddr), "l"(gptr))

// ---------------------------------------------------------------------------
// Prep: normalize -> fp16. 4 rows per warp. Also inits sim on q rows.
// ---------------------------------------------------------------------------
__global__ void prep_kernel(const float* __restrict__ q,
                            const float* __restrict__ y,
                            float* __restrict__ sim) {
    int gw   = (blockIdx.x * blockDim.x + threadIdx.x) >> 5;
    int lane = threadIdx.x & 31;
    int r    = gw * 4 + (lane >> 3);
    int j    = lane & 7;
    const int rows = BATCH * LQ;
    if (r >= 2 * rows) return;
    bool isQ = r < rows;
    int row  = isQ ? r : r - rows;

    const float4* src = (const float4*)((isQ ? q : y) + (size_t)row * DIM);
    float4 v1 = src[j * 2];
    float4 v2 = src[j * 2 + 1];
    float ss = v1.x * v1.x + v1.y * v1.y + v1.z * v1.z + v1.w * v1.w +
               v2.x * v2.x + v2.y * v2.y + v2.z * v2.z + v2.w * v2.w;
    ss += __shfl_xor_sync(0xffffffffu, ss, 1);
    ss += __shfl_xor_sync(0xffffffffu, ss, 2);
    ss += __shfl_xor_sync(0xffffffffu, ss, 4);
    float inv = 1.0f / fmaxf(sqrtf(ss), EPSN);

    __half2 h[4];
    h[0] = __floats2half2_rn(v1.x * inv, v1.y * inv);
    h[1] = __floats2half2_rn(v1.z * inv, v1.w * inv);
    h[2] = __floats2half2_rn(v2.x * inv, v2.y * inv);
    h[3] = __floats2half2_rn(v2.z * inv, v2.w * inv);
    __half* dst = (isQ ? g_q : g_y) + (size_t)row * DIM + j * 8;
    *(uint4*)dst = *(uint4*)h;
    if (isQ && j == 0) sim[row] = __int_as_float(0xff800000);
}

// ---------------------------------------------------------------------------
// HMMA GEMM: CTA = 128(q) x 256(y) supertile, 8 warps (4x2), warp 32x64/tile.
// fp16 accumulators (32 regs) -> 3 CTAs/SM (24 warps). Direct epilogue.
// ---------------------------------------------------------------------------
__global__ __launch_bounds__(256, 3)
void gemm_kernel(float* __restrict__ att, float* __restrict__ sim) {
    extern __shared__ char smem[];
    const uint32_t smA = smem_u32(smem);
    const uint32_t smB = smA + TILE_HB;

    const int tid  = threadIdx.x;
    const int lane = tid & 31;
    const int wid  = tid >> 5;
    const int wm   = wid & 3;    // q group (32 rows)
    const int wn   = wid >> 2;   // y group (64 cols)

    const int b   = blockIdx.z;
    const int yt0 = blockIdx.x * 256;
    const int qt  = blockIdx.y * 128;

    // --- async fills: A (1024 float4) + B0|B1 (2048 float4) ---
    const float4* qsrc = (const float4*)(g_q + ((size_t)b * LQ + qt) * DIM);
    const float4* ysrc = (const float4*)(g_y + ((size_t)b * LY + yt0) * DIM);
#pragma unroll
    for (int it = 0; it < 4; it++) {
        int idx = it * 256 + tid;
        int row = idx >> 3, c = idx & 7;
        CP_ASYNC_CG16(smA + row * (RS * 2) + c * 16, qsrc + idx);
    }
#pragma unroll
    for (int it = 0; it < 8; it++) {
        int idx = it * 256 + tid;
        int row = idx >> 3, c = idx & 7;
        CP_ASYNC_CG16(smB + row * (RS * 2) + c * 16, ysrc + idx);
    }
    asm volatile("cp.async.commit_group;" ::: "memory");

    uint32_t aaddr[2];
#pragma unroll
    for (int mi = 0; mi < 2; mi++) {
        int row = wm * 32 + mi * 16 + (lane & 15);
        aaddr[mi] = smA + row * (RS * 2) + ((lane >> 4) & 1) * 16;
    }
    uint32_t baddr[4];
#pragma unroll
    for (int np = 0; np < 4; np++) {
        int n = wn * 64 + np * 16 + (lane & 7) + ((lane >> 4) & 1) * 8;
        baddr[np] = smB + n * (RS * 2) + ((lane >> 3) & 1) * 16;
    }

    asm volatile("cp.async.wait_group 0;" ::: "memory");
    __syncthreads();

    const int qlane = lane >> 2;
    const int npair = lane & 3;

#pragma unroll
    for (int t = 0; t < 2; t++) {
        const uint32_t bB = t * TILE_HB;
        uint32_t acc[2][8][2];   // packed half2 accumulators (32 regs)
#pragma unroll
        for (int mi = 0; mi < 2; mi++)
#pragma unroll
            for (int ni = 0; ni < 8; ni++) {
                acc[mi][ni][0] = 0u;
                acc[mi][ni][1] = 0u;
            }

#pragma unroll
        for (int ks = 0; ks < 4; ks++) {
            uint32_t bf[8][2];
#pragma unroll
            for (int np = 0; np < 4; np++)
                LDSM_X4(bf[2 * np][0], bf[2 * np][1], bf[2 * np + 1][0],
                        bf[2 * np + 1][1], baddr[np] + bB + ks * 32);
            uint32_t a[2][4];
#pragma unroll
            for (int mi = 0; mi < 2; mi++)
                LDSM_X4(a[mi][0], a[mi][1], a[mi][2], a[mi][3],
                        aaddr[mi] + ks * 32);
#pragma unroll
            for (int mi = 0; mi < 2; mi++)
#pragma unroll
                for (int ni = 0; ni < 8; ni++)
                    MMA_F16ACC(acc[mi][ni], a[mi], bf[ni]);
        }

        // --- Epilogue: convert half2 -> float2, direct streaming stores ---
        const int yt = yt0 + t * 128;
#pragma unroll
        for (int mi = 0; mi < 2; mi++) {
#pragma unroll
            for (int h = 0; h < 2; h++) {
                int qrow = qt + wm * 32 + mi * 16 + h * 8 + qlane;
                float* outr = att + ((size_t)b * LQ + qrow) * LY + yt +
                              wn * 64 + npair * 2;
                __half2 hm = __halves2half2(__ushort_as_half(0xFC00),
                                            __ushort_as_half(0xFC00)); // -inf
#pragma unroll
                for (int ni = 0; ni < 8; ni++) {
                    __half2 hv = *(__half2*)&acc[mi][ni][h];
                    float2 fv = __half22float2(hv);
                    __stcs((float2*)(outr + ni * 8), fv);
                    hm = __hmax2(hm, hv);
                }
                float m = fmaxf(__half2float(__low2half(hm)),
                                __half2float(__high2half(hm)));
                m = fmaxf(m, __shfl_xor_sync(0xffffffffu, m, 1));
                m = fmaxf(m, __shfl_xor_sync(0xffffffffu, m, 2));
                if (npair == 0)
                    atomicMaxFloat(&sim[(size_t)b * LQ + qrow], m);
            }
        }
    }
}

// ---------------------------------------------------------------------------
extern "C" void kernel_launch(void* const* d_in, const int* in_sizes, int n_in,
                              void* d_out, int out_size) {
    const float* q = (const float*)d_in[0];
    const float* y = (const float*)d_in[1];
    float* att = (float*)d_out;
    float* sim = att + (size_t)BATCH * LQ * LY;

    static bool attr_done = false;
    if (!attr_done) {
        cudaFuncSetAttribute(gemm_kernel,
                             cudaFuncAttributeMaxDynamicSharedMemorySize,
                             SM_TOTAL);
        attr_done = true;
    }

    int warps = (2 * BATCH * LQ) / 4;
    prep_kernel<<<(warps * 32 + 255) / 256, 256>>>(q, y, sim);

    dim3 grid(LY / 256, LQ / 128, BATCH);   // (8, 16, 8) = 1024 CTAs
    gemm_kernel<<<grid, 256, SM_TOTAL>>>(att, sim);
}

// round 15
// speedup vs baseline: 1.1769x; 1.0621x over previous
#include <cuda_runtime.h>
#include <cuda_fp16.h>
#include <cstdint>

#define BATCH 8
#define LQ 2048
#define LY 2048
#define DIM 64
#define EPSN 1e-8f

#define RS 72                    // tile row stride in halves (144 B)
#define TILE_HB (128 * RS * 2)   // 18432 B per tile
#define SM_TOTAL (3 * TILE_HB)   // A + 2 B tiles = 55296 B dynamic smem

// fp16 normalized operands (input quant ~2.9e-4; +fp16 acc -> ~4.4e-4 measured)
__device__ __half g_q[(size_t)BATCH * LQ * DIM];
__device__ __half g_y[(size_t)BATCH * LY * DIM];

__device__ __forceinline__ uint32_t smem_u32(const void* p) {
    uint32_t a;
    asm("{ .reg .u64 t; cvta.to.shared.u64 t, %1; cvt.u32.u64 %0, t; }"
        : "=r"(a) : "l"(p));
    return a;
}
__device__ __forceinline__ void atomicMaxFloat(float* addr, float v) {
    if (v >= 0.0f)
        atomicMax((int*)addr, __float_as_int(v));
    else
        atomicMin((unsigned int*)addr, __float_as_uint(v));
}

#define LDSM_X4(r0, r1, r2, r3, addr)                                          \
    asm volatile("ldmatrix.sync.aligned.m8n8.x4.shared.b16 {%0,%1,%2,%3}, [%4];" \
                 : "=r"(r0), "=r"(r1), "=r"(r2), "=r"(r3) : "r"(addr))

// fp16-accumulator MMA: D/C are 2 packed half2 regs (rows l>>2 and l>>2+8).
#define MMA_F16ACC(d, a, bf)                                                   \
    asm volatile(                                                              \
        "mma.sync.aligned.m16n8k16.row.col.f16.f16.f16.f16 "                  \
        "{%0,%1}, {%2,%3,%4,%5}, {%6,%7}, {%0,%1};"                           \
        : "+r"(d[0]), "+r"(d[1])                                               \
        : "r"(a[0]), "r"(a[1]), "r"(a[2]), "r"(a[3]), "r"(bf[0]), "r"(bf[1]))

#define CP_ASYNC_CG16(smaddr, gptr)                                            \
    asm volatile("cp.async.cg.shared.global [%0], [%1], 16;"                    \
                 :: "r"(smaddr), "l"(gptr))

// ---------------------------------------------------------------------------
// Prep: normalize -> fp16. 4 rows per warp. Also inits sim on q rows.
// ---------------------------------------------------------------------------
__global__ void prep_kernel(const float* __restrict__ q,
                            const float* __restrict__ y,
                            float* __restrict__ sim) {
    int gw   = (blockIdx.x * blockDim.x + threadIdx.x) >> 5;
    int lane = threadIdx.x & 31;
    int r    = gw * 4 + (lane >> 3);
    int j    = lane & 7;
    const int rows = BATCH * LQ;
    if (r >= 2 * rows) return;
    bool isQ = r < rows;
    int row  = isQ ? r : r - rows;

    const float4* src = (const float4*)((isQ ? q : y) + (size_t)row * DIM);
    float4 v1 = src[j * 2];
    float4 v2 = src[j * 2 + 1];
    float ss = v1.x * v1.x + v1.y * v1.y + v1.z * v1.z + v1.w * v1.w +
               v2.x * v2.x + v2.y * v2.y + v2.z * v2.z + v2.w * v2.w;
    ss += __shfl_xor_sync(0xffffffffu, ss, 1);
    ss += __shfl_xor_sync(0xffffffffu, ss, 2);
    ss += __shfl_xor_sync(0xffffffffu, ss, 4);
    float inv = 1.0f / fmaxf(sqrtf(ss), EPSN);

    __half2 h[4];
    h[0] = __floats2half2_rn(v1.x * inv, v1.y * inv);
    h[1] = __floats2half2_rn(v1.z * inv, v1.w * inv);
    h[2] = __floats2half2_rn(v2.x * inv, v2.y * inv);
    h[3] = __floats2half2_rn(v2.z * inv, v2.w * inv);
    __half* dst = (isQ ? g_q : g_y) + (size_t)row * DIM + j * 8;
    *(uint4*)dst = *(uint4*)h;
    if (isQ && j == 0) sim[row] = __int_as_float(0xff800000);
}

// ---------------------------------------------------------------------------
// HMMA GEMM: CTA = 128(q) x 256(y) supertile, 8 warps (4x2), warp 32x64/tile,
// fp16 accumulators, 3 CTAs/SM. Epilogue: single-shfl quad pairing -> STG.128.
// ---------------------------------------------------------------------------
__global__ __launch_bounds__(256, 3)
void gemm_kernel(float* __restrict__ att, float* __restrict__ sim) {
    extern __shared__ char smem[];
    const uint32_t smA = smem_u32(smem);
    const uint32_t smB = smA + TILE_HB;

    const int tid  = threadIdx.x;
    const int lane = tid & 31;
    const int wid  = tid >> 5;
    const int wm   = wid & 3;    // q group (32 rows)
    const int wn   = wid >> 2;   // y group (64 cols)

    const int b   = blockIdx.z;
    const int yt0 = blockIdx.x * 256;
    const int qt  = blockIdx.y * 128;

    // --- async fills: A (1024 float4) + B0|B1 (2048 float4) ---
    const float4* qsrc = (const float4*)(g_q + ((size_t)b * LQ + qt) * DIM);
    const float4* ysrc = (const float4*)(g_y + ((size_t)b * LY + yt0) * DIM);
#pragma unroll
    for (int it = 0; it < 4; it++) {
        int idx = it * 256 + tid;
        int row = idx >> 3, c = idx & 7;
        CP_ASYNC_CG16(smA + row * (RS * 2) + c * 16, qsrc + idx);
    }
#pragma unroll
    for (int it = 0; it < 8; it++) {
        int idx = it * 256 + tid;
        int row = idx >> 3, c = idx & 7;
        CP_ASYNC_CG16(smB + row * (RS * 2) + c * 16, ysrc + idx);
    }
    asm volatile("cp.async.commit_group;" ::: "memory");

    uint32_t aaddr[2];
#pragma unroll
    for (int mi = 0; mi < 2; mi++) {
        int row = wm * 32 + mi * 16 + (lane & 15);
        aaddr[mi] = smA + row * (RS * 2) + ((lane >> 4) & 1) * 16;
    }
    uint32_t baddr[4];
#pragma unroll
    for (int np = 0; np < 4; np++) {
        int n = wn * 64 + np * 16 + (lane & 7) + ((lane >> 4) & 1) * 8;
        baddr[np] = smB + n * (RS * 2) + ((lane >> 3) & 1) * 16;
    }

    asm volatile("cp.async.wait_group 0;" ::: "memory");
    __syncthreads();

    const int qlane = lane >> 2;
    const int npair = lane & 3;
    const bool podd = npair & 1;              // odd member of the xor-1 pair
    // store column base offset within the 16-col k-group (compile-time shape)
    const int coloff = 2 * npair + (podd ? 6 : 0);

#pragma unroll
    for (int t = 0; t < 2; t++) {
        const uint32_t bB = t * TILE_HB;
        uint32_t acc[2][8][2];   // packed half2 accumulators (32 regs)
#pragma unroll
        for (int mi = 0; mi < 2; mi++)
#pragma unroll
            for (int ni = 0; ni < 8; ni++) {
                acc[mi][ni][0] = 0u;
                acc[mi][ni][1] = 0u;
            }

#pragma unroll
        for (int ks = 0; ks < 4; ks++) {
            uint32_t bf[8][2];
#pragma unroll
            for (int np = 0; np < 4; np++)
                LDSM_X4(bf[2 * np][0], bf[2 * np][1], bf[2 * np + 1][0],
                        bf[2 * np + 1][1], baddr[np] + bB + ks * 32);
            uint32_t a[2][4];
#pragma unroll
            for (int mi = 0; mi < 2; mi++)
                LDSM_X4(a[mi][0], a[mi][1], a[mi][2], a[mi][3],
                        aaddr[mi] + ks * 32);
#pragma unroll
            for (int mi = 0; mi < 2; mi++)
#pragma unroll
                for (int ni = 0; ni < 8; ni++)
                    MMA_F16ACC(acc[mi][ni], a[mi], bf[ni]);
        }

        // --- Epilogue: quad-pair exchange (1 shfl) -> STG.128 + row-max ---
        const int yt = yt0 + t * 128;
#pragma unroll
        for (int mi = 0; mi < 2; mi++) {
#pragma unroll
            for (int h = 0; h < 2; h++) {
                int qrow = qt + wm * 32 + mi * 16 + h * 8 + qlane;
                float* outrow =
                    att + ((size_t)b * LQ + qrow) * LY + yt + wn * 64;

                // row max over this thread's 16 cols (packed half2 max)
                __half2 hm = __halves2half2(__ushort_as_half(0xFC00),
                                            __ushort_as_half(0xFC00));
#pragma unroll
                for (int ni = 0; ni < 8; ni++)
                    hm = __hmax2(hm, *(__half2*)&acc[mi][ni][h]);
                float m = fmaxf(__half2float(__low2half(hm)),
                                __half2float(__high2half(hm)));
                m = fmaxf(m, __shfl_xor_sync(0xffffffffu, m, 1));
                m = fmaxf(m, __shfl_xor_sync(0xffffffffu, m, 2));
                if (npair == 0)
                    atomicMaxFloat(&sim[(size_t)b * LQ + qrow], m);

#pragma unroll
                for (int k = 0; k < 4; k++) {
                    uint32_t ev = acc[mi][2 * k][h];       // ni even (static)
                    uint32_t od = acc[mi][2 * k + 1][h];   // ni odd  (static)
                    // even lane sends its odd-ni reg; odd lane its even-ni reg
                    uint32_t send = podd ? ev : od;
                    uint32_t recv = __shfl_xor_sync(0xffffffffu, send, 1);
                    float2 own = __half22float2(
                        *(__half2*)(podd ? &od : &ev));
                    float2 oth = __half22float2(*(__half2*)&recv);
                    float4 v = podd ? make_float4(oth.x, oth.y, own.x, own.y)
                                    : make_float4(own.x, own.y, oth.x, oth.y);
                    __stcs((float4*)(outrow + 16 * k + coloff), v);
                }
            }
        }
    }
}

// ---------------------------------------------------------------------------
extern "C" void kernel_launch(void* const* d_in, const int* in_sizes, int n_in,
                              void* d_out, int out_size) {
    const float* q = (const float*)d_in[0];
    const float* y = (const float*)d_in[1];
    float* att = (float*)d_out;
    float* sim = att + (size_t)BATCH * LQ * LY;

    static bool attr_done = false;
    if (!attr_done) {
        cudaFuncSetAttribute(gemm_kernel,
                             cudaFuncAttributeMaxDynamicSharedMemorySize,
                             SM_TOTAL);
        attr_done = true;
    }

    int warps = (2 * BATCH * LQ) / 4;
    prep_kernel<<<(warps * 32 + 255) / 256, 256>>>(q, y, sim);

    dim3 grid(LY / 256, LQ / 128, BATCH);   // (8, 16, 8) = 1024 CTAs
    gemm_kernel<<<grid, 256, SM_TOTAL>>>(att, sim);
}

// round 16
// speedup vs baseline: 1.1837x; 1.0058x over previous
#include <cuda_runtime.h>
#include <cuda_fp16.h>
#include <cstdint>

#define BATCH 8
#define LQ 2048
#define LY 2048
#define DIM 64
#define EPSN 1e-8f

#define RS 72                    // tile row stride in halves (144 B)
#define TILE_HB (128 * RS * 2)   // 18432 B per tile
#define SM_TOTAL (3 * TILE_HB)   // A + 2 B tiles = 55296 B dynamic smem

// fp16 normalized operands (input quant ~2.9e-4; +fp16 acc -> 4.4e-4 measured)
__device__ __half g_q[(size_t)BATCH * LQ * DIM];
__device__ __half g_y[(size_t)BATCH * LY * DIM];

__device__ __forceinline__ uint32_t smem_u32(const void* p) {
    uint32_t a;
    asm("{ .reg .u64 t; cvta.to.shared.u64 t, %1; cvt.u32.u64 %0, t; }"
        : "=r"(a) : "l"(p));
    return a;
}
__device__ __forceinline__ void atomicMaxFloat(float* addr, float v) {
    if (v >= 0.0f)
        atomicMax((int*)addr, __float_as_int(v));
    else
        atomicMin((unsigned int*)addr, __float_as_uint(v));
}

#define LDSM_X4(r0, r1, r2, r3, addr)                                          \
    asm volatile("ldmatrix.sync.aligned.m8n8.x4.shared.b16 {%0,%1,%2,%3}, [%4];" \
                 : "=r"(r0), "=r"(r1), "=r"(r2), "=r"(r3) : "r"(addr))

// fp16-accumulator MMA: D/C are 2 packed half2 regs (rows l>>2 and l>>2+8).
#define MMA_F16ACC(d, a, bf)                                                   \
    asm volatile(                                                              \
        "mma.sync.aligned.m16n8k16.row.col.f16.f16.f16.f16 "                  \
        "{%0,%1}, {%2,%3,%4,%5}, {%6,%7}, {%0,%1};"                           \
        : "+r"(d[0]), "+r"(d[1])                                               \
        : "r"(a[0]), "r"(a[1]), "r"(a[2]), "r"(a[3]), "r"(bf[0]), "r"(bf[1]))

#define CP_ASYNC_CG16(smaddr, gptr)                                            \
    asm volatile("cp.async.cg.shared.global [%0], [%1], 16;"                    \
                 :: "r"(smaddr), "l"(gptr))

// y-column permutation within each 64-row B group: output col c -> MMA slot.
// slot = 16*(c>>4) + 8*((c>>1)&1) + 2*((c>>2)&3) + (c&1)
__device__ __forceinline__ int bperm(int c) {
    return (c & 48) + ((c & 2) << 2) + ((c & 12) >> 1) + (c & 1);
}

// ---------------------------------------------------------------------------
// Prep: normalize -> fp16. 4 rows per warp. Also inits sim on q rows.
// ---------------------------------------------------------------------------
__global__ void prep_kernel(const float* __restrict__ q,
                            const float* __restrict__ y,
                            float* __restrict__ sim) {
    int gw   = (blockIdx.x * blockDim.x + threadIdx.x) >> 5;
    int lane = threadIdx.x & 31;
    int r    = gw * 4 + (lane >> 3);
    int j    = lane & 7;
    const int rows = BATCH * LQ;
    if (r >= 2 * rows) return;
    bool isQ = r < rows;
    int row  = isQ ? r : r - rows;

    const float4* src = (const float4*)((isQ ? q : y) + (size_t)row * DIM);
    float4 v1 = src[j * 2];
    float4 v2 = src[j * 2 + 1];
    float ss = v1.x * v1.x + v1.y * v1.y + v1.z * v1.z + v1.w * v1.w +
               v2.x * v2.x + v2.y * v2.y + v2.z * v2.z + v2.w * v2.w;
    ss += __shfl_xor_sync(0xffffffffu, ss, 1);
    ss += __shfl_xor_sync(0xffffffffu, ss, 2);
    ss += __shfl_xor_sync(0xffffffffu, ss, 4);
    float inv = 1.0f / fmaxf(sqrtf(ss), EPSN);

    __half2 h[4];
    h[0] = __floats2half2_rn(v1.x * inv, v1.y * inv);
    h[1] = __floats2half2_rn(v1.z * inv, v1.w * inv);
    h[2] = __floats2half2_rn(v2.x * inv, v2.y * inv);
    h[3] = __floats2half2_rn(v2.z * inv, v2.w * inv);
    __half* dst = (isQ ? g_q : g_y) + (size_t)row * DIM + j * 8;
    *(uint4*)dst = *(uint4*)h;
    if (isQ && j == 0) sim[row] = __int_as_float(0xff800000);
}

// ---------------------------------------------------------------------------
// HMMA GEMM: CTA = 128(q) x 256(y) supertile, 8 warps (4x2), warp 32x64/tile,
// fp16 accumulators, 3 CTAs/SM. Column-permuted B layout makes each quad
// lane's accumulators 16 consecutive output cols -> pure STG.128 epilogue.
// ---------------------------------------------------------------------------
__global__ __launch_bounds__(256, 3)
void gemm_kernel(float* __restrict__ att, float* __restrict__ sim) {
    extern __shared__ char smem[];
    const uint32_t smA = smem_u32(smem);
    const uint32_t smB = smA + TILE_HB;

    const int tid  = threadIdx.x;
    const int lane = tid & 31;
    const int wid  = tid >> 5;
    const int wm   = wid & 3;    // q group (32 rows)
    const int wn   = wid >> 2;   // y group (64 cols)

    const int b   = blockIdx.z;
    const int yt0 = blockIdx.x * 256;
    const int qt  = blockIdx.y * 128;

    // --- async fills: A (1024 float4) + B0|B1 (2048 float4, permuted rows) ---
    const float4* qsrc = (const float4*)(g_q + ((size_t)b * LQ + qt) * DIM);
    const float4* ysrc = (const float4*)(g_y + ((size_t)b * LY + yt0) * DIM);
#pragma unroll
    for (int it = 0; it < 4; it++) {
        int idx = it * 256 + tid;
        int row = idx >> 3, c = idx & 7;
        CP_ASYNC_CG16(smA + row * (RS * 2) + c * 16, qsrc + idx);
    }
#pragma unroll
    for (int it = 0; it < 8; it++) {
        int idx = it * 256 + tid;
        int n = idx >> 3, c = idx & 7;
        int rowp = (n & ~63) + bperm(n & 63);   // permute within 64-row group
        CP_ASYNC_CG16(smB + rowp * (RS * 2) + c * 16, ysrc + idx);
    }
    asm volatile("cp.async.commit_group;" ::: "memory");

    uint32_t aaddr[2];
#pragma unroll
    for (int mi = 0; mi < 2; mi++) {
        int row = wm * 32 + mi * 16 + (lane & 15);
        aaddr[mi] = smA + row * (RS * 2) + ((lane >> 4) & 1) * 16;
    }
    uint32_t baddr[4];
#pragma unroll
    for (int np = 0; np < 4; np++) {
        int n = wn * 64 + np * 16 + (lane & 7) + ((lane >> 4) & 1) * 8;
        baddr[np] = smB + n * (RS * 2) + ((lane >> 3) & 1) * 16;
    }

    asm volatile("cp.async.wait_group 0;" ::: "memory");
    __syncthreads();

    const int qlane = lane >> 2;
    const int npair = lane & 3;

#pragma unroll
    for (int t = 0; t < 2; t++) {
        const uint32_t bB = t * TILE_HB;
        uint32_t acc[2][8][2];   // packed half2 accumulators (32 regs)
#pragma unroll
        for (int mi = 0; mi < 2; mi++)
#pragma unroll
            for (int ni = 0; ni < 8; ni++) {
                acc[mi][ni][0] = 0u;
                acc[mi][ni][1] = 0u;
            }

#pragma unroll
        for (int ks = 0; ks < 4; ks++) {
            uint32_t bf[8][2];
#pragma unroll
            for (int np = 0; np < 4; np++)
                LDSM_X4(bf[2 * np][0], bf[2 * np][1], bf[2 * np + 1][0],
                        bf[2 * np + 1][1], baddr[np] + bB + ks * 32);
            uint32_t a[2][4];
#pragma unroll
            for (int mi = 0; mi < 2; mi++)
                LDSM_X4(a[mi][0], a[mi][1], a[mi][2], a[mi][3],
                        aaddr[mi] + ks * 32);
#pragma unroll
            for (int mi = 0; mi < 2; mi++)
#pragma unroll
                for (int ni = 0; ni < 8; ni++)
                    MMA_F16ACC(acc[mi][ni], a[mi], bf[ni]);
        }

        // --- Epilogue: direct STG.128 (permuted ownership) + fused row-max ---
        const int yt = yt0 + t * 128;
#pragma unroll
        for (int mi = 0; mi < 2; mi++) {
#pragma unroll
            for (int h = 0; h < 2; h++) {
                int qrow = qt + wm * 32 + mi * 16 + h * 8 + qlane;
                float* outrow =
                    att + ((size_t)b * LQ + qrow) * LY + yt + wn * 64;

                // row max over this thread's 16 cols (packed half2 max)
                __half2 hm = __halves2half2(__ushort_as_half(0xFC00),
                                            __ushort_as_half(0xFC00));
#pragma unroll
                for (int ni = 0; ni < 8; ni++)
                    hm = __hmax2(hm, *(__half2*)&acc[mi][ni][h]);
                float m = fmaxf(__half2float(__low2half(hm)),
                                __half2float(__high2half(hm)));
                m = fmaxf(m, __shfl_xor_sync(0xffffffffu, m, 1));
                m = fmaxf(m, __shfl_xor_sync(0xffffffffu, m, 2));
                if (npair == 0)
                    atomicMaxFloat(&sim[(size_t)b * LQ + qrow], m);

                // lane npair owns cols 16k+4*npair..+3 for k=0..3 (static idx)
#pragma unroll
                for (int k = 0; k < 4; k++) {
                    float2 f2 = __half22float2(*(__half2*)&acc[mi][2 * k][h]);
                    float2 g2 =
                        __half22float2(*(__half2*)&acc[mi][2 * k + 1][h]);
                    __stcs((float4*)(outrow + 16 * k + 4 * npair),
                           make_float4(f2.x, f2.y, g2.x, g2.y));
                }
            }
        }
    }
}

// ---------------------------------------------------------------------------
extern "C" void kernel_launch(void* const* d_in, const int* in_sizes, int n_in,
                              void* d_out, int out_size) {
    const float* q = (const float*)d_in[0];
    const float* y = (const float*)d_in[1];
    float* att = (float*)d_out;
    float* sim = att + (size_t)BATCH * LQ * LY;

    static bool attr_done = false;
    if (!attr_done) {
        cudaFuncSetAttribute(gemm_kernel,
                             cudaFuncAttributeMaxDynamicSharedMemorySize,
                             SM_TOTAL);
        attr_done = true;
    }

    int warps = (2 * BATCH * LQ) / 4;
    prep_kernel<<<(warps * 32 + 255) / 256, 256>>>(q, y, sim);

    dim3 grid(LY / 256, LQ / 128, BATCH);   // (8, 16, 8) = 1024 CTAs
    gemm_kernel<<<grid, 256, SM_TOTAL>>>(att, sim);
}